// round 1
// baseline (speedup 1.0000x reference)
#include <cuda_runtime.h>
#include <cstdint>

// Problem constants
#define B_    16
#define T_    8
#define KBANK 64
#define COUT  128
#define CIN   128
#define KH    5
#define KW    5
#define HH    64
#define WW    64
#define PADR  2
#define PPW   (COUT * CIN * KH * KW)   // 409600 weight elems per (b) / per (k)

// Scratch (device globals: allocation-free per harness rules)
__device__ float g_coeff[B_ * KBANK];                  // 1024 floats
__device__ float g_lp[(size_t)B_ * PPW];               // 26.2 MB per-batch conv weights

// ---------------------------------------------------------------------------
// Kernel 0: coeff[b,k] = (1/T) * sum_t tf[b,t,k]
// ---------------------------------------------------------------------------
__global__ void coeff_kernel(const float* __restrict__ tf) {
    int tid = threadIdx.x;              // 0..1023
    int b = tid >> 6;                   // /64
    int k = tid & 63;
    float s = 0.f;
#pragma unroll
    for (int t = 0; t < T_; t++)
        s += tf[((b * T_ + t) * KBANK) + k];
    g_coeff[tid] = s * (1.0f / (float)T_);
}

// ---------------------------------------------------------------------------
// Kernel 1: g_lp[b][p] = sum_k coeff[b][k] * W[k][p],  p in [0, 409600)
// One thread per p; 16 batch accumulators in registers; W streamed once.
// ---------------------------------------------------------------------------
__global__ __launch_bounds__(256) void lp_kernel(const float* __restrict__ W) {
    __shared__ float sc[B_ * KBANK];    // 4 KB
    int tid = threadIdx.x;
#pragma unroll
    for (int i = tid; i < B_ * KBANK; i += 256)
        sc[i] = g_coeff[i];
    __syncthreads();

    size_t p = (size_t)blockIdx.x * 256 + tid;   // < 409600
    float acc[B_];
#pragma unroll
    for (int b = 0; b < B_; b++) acc[b] = 0.f;

    for (int k = 0; k < KBANK; k++) {
        float wv = W[(size_t)k * PPW + p];
#pragma unroll
        for (int b = 0; b < B_; b++)
            acc[b] = fmaf(sc[b * KBANK + k], wv, acc[b]);
    }
#pragma unroll
    for (int b = 0; b < B_; b++)
        g_lp[(size_t)b * PPW + p] = acc[b];
}

// ---------------------------------------------------------------------------
// Kernel 2: per-batch 5x5 conv, pad 2.
// Block: one batch b, TO=32 output channels, spatial tile TH=8 x TW=32.
// Thread: one output pixel, 32 channel accumulators.
// Loop over CIN in chunks of CC=8: stage x halo tile + weight slice in smem.
// ---------------------------------------------------------------------------
#define TH 8
#define TW 32
#define TO 32
#define CC 8
#define XROW (TW + 4)     // 36
#define XCOL (TH + 4)     // 12

__global__ __launch_bounds__(256) void conv_kernel(const float* __restrict__ x,
                                                   float* __restrict__ out) {
    __shared__ float sx[CC][XCOL][XROW];     // 8*12*36*4 = 13.8 KB
    __shared__ float sw[TO][CC * KH * KW];   // 32*200*4  = 25.6 KB

    const int b    = blockIdx.z;
    const int o0   = blockIdx.y * TO;
    const int tile = blockIdx.x;             // 0..15
    const int th0  = (tile >> 1) * TH;       // 8 tiles in y
    const int tw0  = (tile & 1) * TW;        // 2 tiles in x
    const int tid  = threadIdx.x;
    const int ty   = tid >> 5;               // 0..7
    const int tx   = tid & 31;               // 0..31  (warp = one 32-wide row)

    float acc[TO];
#pragma unroll
    for (int o = 0; o < TO; o++) acc[o] = 0.f;

    const float* xb  = x + (size_t)b * CIN * HH * WW;
    const float* lpb = g_lp + (size_t)b * PPW + (size_t)o0 * (CIN * KH * KW);

    for (int c0 = 0; c0 < CIN; c0 += CC) {
        // ---- stage x halo tile (zero-padded borders) ----
        for (int idx = tid; idx < CC * XCOL * XROW; idx += 256) {
            int cc = idx / (XCOL * XROW);
            int r  = idx % (XCOL * XROW);
            int lh = r / XROW;
            int lw = r % XROW;
            int gh = th0 + lh - PADR;
            int gw = tw0 + lw - PADR;
            float v = 0.f;
            if (gh >= 0 && gh < HH && gw >= 0 && gw < WW)
                v = xb[((size_t)(c0 + cc) * HH + gh) * WW + gw];
            sx[cc][lh][lw] = v;
        }
        // ---- stage weight slice: sw[o][cc*25+ij], contiguous global run per o ----
        for (int idx = tid; idx < TO * CC * KH * KW; idx += 256) {
            int o = idx / (CC * KH * KW);
            int r = idx % (CC * KH * KW);            // cc*25 + ij
            sw[o][r] = lpb[(size_t)o * (CIN * KH * KW) + (size_t)c0 * (KH * KW) + r];
        }
        __syncthreads();

        // ---- accumulate: per x value, broadcast 32 weights + 32 FFMA ----
        for (int cc = 0; cc < CC; cc++) {
#pragma unroll
            for (int i = 0; i < KH; i++) {
#pragma unroll
                for (int j = 0; j < KW; j++) {
                    float xv = sx[cc][ty + i][tx + j];
#pragma unroll
                    for (int o = 0; o < TO; o++)
                        acc[o] = fmaf(xv, sw[o][cc * 25 + i * 5 + j], acc[o]);
                }
            }
        }
        __syncthreads();
    }

    // ---- write out (coalesced across tx) ----
    const int gh = th0 + ty;
    const int gw = tw0 + tx;
    float* ob = out + ((size_t)b * COUT + o0) * HH * WW;
#pragma unroll
    for (int o = 0; o < TO; o++)
        ob[(size_t)o * HH * WW + (size_t)gh * WW + gw] = acc[o];
}

// ---------------------------------------------------------------------------
extern "C" void kernel_launch(void* const* d_in, const int* in_sizes, int n_in,
                              void* d_out, int out_size) {
    (void)in_sizes; (void)n_in; (void)out_size;
    const float* x  = (const float*)d_in[0];   // (16,128,64,64)
    const float* tf = (const float*)d_in[1];   // (16,8,64)
    const float* W  = (const float*)d_in[2];   // (64,128,128,5,5)
    float* out = (float*)d_out;                // (16,128,64,64)

    coeff_kernel<<<1, 1024>>>(tf);
    lp_kernel<<<PPW / 256, 256>>>(W);          // 1600 blocks
    dim3 grid(16, COUT / TO, B_);              // (spatial tiles, o-blocks, batch)
    conv_kernel<<<grid, 256>>>(x, out);
}

// round 2
// speedup vs baseline: 2.3042x; 2.3042x over previous
#include <cuda_runtime.h>
#include <cstdint>

// Problem constants
#define B_    16
#define T_    8
#define KBANK 64
#define COUT  128
#define CIN   128
#define KH    5
#define KW    5
#define HH    64
#define WW    64
#define PADR  2
#define PPW   (COUT * CIN * KH * KW)   // 409600

typedef unsigned long long ull;

// packed f32x2 helpers (Blackwell-only; ptxas never auto-fuses these)
#define FMA2(d, a, b, c) asm("fma.rn.f32x2 %0, %1, %2, %3;" : "=l"(d) : "l"(a), "l"(b), "l"(c))
#define PACK_DUP(d, x)   asm("mov.b64 %0, {%1, %1};" : "=l"(d) : "f"(x))
#define UNPACK2(lo, hi, v) asm("mov.b64 {%0, %1}, %2;" : "=f"(lo), "=f"(hi) : "l"(v))

// Scratch (device globals: allocation-free per harness rules)
__device__ float g_coeff[B_ * KBANK];
__device__ float g_lp[(size_t)B_ * PPW];     // 26.2 MB per-batch conv weights

// ---------------------------------------------------------------------------
// Kernel 0: coeff[b,k] = (1/T) * sum_t tf[b,t,k]
// ---------------------------------------------------------------------------
__global__ void coeff_kernel(const float* __restrict__ tf) {
    int tid = threadIdx.x;              // 0..1023
    int b = tid >> 6;
    int k = tid & 63;
    float s = 0.f;
#pragma unroll
    for (int t = 0; t < T_; t++)
        s += tf[((b * T_ + t) * KBANK) + k];
    g_coeff[tid] = s * (1.0f / (float)T_);
}

// ---------------------------------------------------------------------------
// Kernel 1: g_lp[b][p] = sum_k coeff[b][k] * W[k][p]   (memory-bound, W once)
// ---------------------------------------------------------------------------
__global__ __launch_bounds__(256) void lp_kernel(const float* __restrict__ W) {
    __shared__ float sc[B_ * KBANK];
    int tid = threadIdx.x;
#pragma unroll
    for (int i = tid; i < B_ * KBANK; i += 256)
        sc[i] = g_coeff[i];
    __syncthreads();

    size_t p = (size_t)blockIdx.x * 256 + tid;
    float acc[B_];
#pragma unroll
    for (int b = 0; b < B_; b++) acc[b] = 0.f;

    for (int k = 0; k < KBANK; k++) {
        float wv = W[(size_t)k * PPW + p];
#pragma unroll
        for (int b = 0; b < B_; b++)
            acc[b] = fmaf(sc[b * KBANK + k], wv, acc[b]);
    }
#pragma unroll
    for (int b = 0; b < B_; b++)
        g_lp[(size_t)b * PPW + p] = acc[b];
}

// ---------------------------------------------------------------------------
// Kernel 2: per-batch 5x5 conv, pad 2 — FFMA2 register-tiled version.
// Block: batch b, TOC=8 output channels, 32x32 spatial tile, 256 threads.
// Thread: 4 adjacent pixels x 8 channels = 16 f32x2 accumulators.
// CIN chunked by CC=4; x halo + weight slice staged in smem.
// ---------------------------------------------------------------------------
#define TOC 8
#define TSP 32
#define CC  4
#define XH  36          // TSP + 4 halo
#define XP  37          // padded pitch -> conflict-free LDS pattern

__global__ __launch_bounds__(256) void conv_kernel(const float* __restrict__ x,
                                                   float* __restrict__ out) {
    __shared__ float sx[CC][XH][XP];        // 21.3 KB
    __shared__ float swf[CC * 25 * TOC];    // 3.2 KB, layout [(cc*25+ij)*8 + o]

    const int b   = blockIdx.z;
    const int o0  = blockIdx.y * TOC;
    const int th0 = (blockIdx.x >> 1) * TSP;
    const int tw0 = (blockIdx.x & 1) * TSP;
    const int tid = threadIdx.x;
    const int ry  = tid >> 3;               // 0..31: output row in tile
    const int px0 = (tid & 7) * 4;          // output col group (4 px)

    ull acc[4][4];                          // [pixel][channel-pair]
#pragma unroll
    for (int p = 0; p < 4; p++)
#pragma unroll
        for (int q = 0; q < 4; q++) acc[p][q] = 0ULL;   // two packed 0.0f

    const float* xb  = x + (size_t)b * CIN * HH * WW;
    const float* lpb = g_lp + (size_t)b * PPW;

    for (int c0 = 0; c0 < CIN; c0 += CC) {
        // ---- stage x halo tile (zero-padded) ----
        for (int idx = tid; idx < CC * XH * XH; idx += 256) {
            int cc = idx / (XH * XH);
            int r  = idx - cc * (XH * XH);
            int lh = r / XH;
            int lw = r - lh * XH;
            int gh = th0 + lh - PADR;
            int gw = tw0 + lw - PADR;
            float v = 0.f;
            if ((unsigned)gh < HH && (unsigned)gw < WW)
                v = xb[((size_t)(c0 + cc) * HH + gh) * WW + gw];
            sx[cc][lh][lw] = v;
        }
        // ---- stage weights, channel-pair-contiguous for LDS.64 ----
        for (int idx = tid; idx < CC * 25 * TOC; idx += 256) {
            int ij = idx % 25;
            int t  = idx / 25;
            int o  = t & 7;
            int cc = t >> 3;
            swf[(cc * 25 + ij) * 8 + o] =
                lpb[((size_t)(o0 + o) * CIN + (c0 + cc)) * 25 + ij];
        }
        __syncthreads();

#pragma unroll 1
        for (int cc = 0; cc < CC; cc++) {
#pragma unroll 1
            for (int i = 0; i < KH; i++) {
                float xr[8];
#pragma unroll
                for (int m = 0; m < 8; m++)
                    xr[m] = sx[cc][ry + i][px0 + m];
#pragma unroll
                for (int j = 0; j < KW; j++) {
                    ull xd[4];
#pragma unroll
                    for (int p = 0; p < 4; p++) PACK_DUP(xd[p], xr[j + p]);
                    const ull* wp = (const ull*)&swf[(cc * 25 + i * 5 + j) * 8];
                    ull w0 = wp[0], w1 = wp[1], w2 = wp[2], w3 = wp[3];
#pragma unroll
                    for (int p = 0; p < 4; p++) {
                        FMA2(acc[p][0], xd[p], w0, acc[p][0]);
                        FMA2(acc[p][1], xd[p], w1, acc[p][1]);
                        FMA2(acc[p][2], xd[p], w2, acc[p][2]);
                        FMA2(acc[p][3], xd[p], w3, acc[p][3]);
                    }
                }
            }
        }
        __syncthreads();
    }

    // ---- write out: float4 per channel row (16B aligned) ----
    const int gh = th0 + ry;
    float* ob = out + ((size_t)b * COUT + o0) * HH * WW + (size_t)gh * WW + tw0 + px0;
#pragma unroll
    for (int q = 0; q < 4; q++) {
        float lo0, hi0, lo1, hi1, lo2, hi2, lo3, hi3;
        UNPACK2(lo0, hi0, acc[0][q]);
        UNPACK2(lo1, hi1, acc[1][q]);
        UNPACK2(lo2, hi2, acc[2][q]);
        UNPACK2(lo3, hi3, acc[3][q]);
        float4 vlo = make_float4(lo0, lo1, lo2, lo3);
        float4 vhi = make_float4(hi0, hi1, hi2, hi3);
        *(float4*)(ob + (size_t)(2 * q) * HH * WW)     = vlo;
        *(float4*)(ob + (size_t)(2 * q + 1) * HH * WW) = vhi;
    }
}

// ---------------------------------------------------------------------------
extern "C" void kernel_launch(void* const* d_in, const int* in_sizes, int n_in,
                              void* d_out, int out_size) {
    (void)in_sizes; (void)n_in; (void)out_size;
    const float* x  = (const float*)d_in[0];   // (16,128,64,64)
    const float* tf = (const float*)d_in[1];   // (16,8,64)
    const float* W  = (const float*)d_in[2];   // (64,128,128,5,5)
    float* out = (float*)d_out;                // (16,128,64,64)

    coeff_kernel<<<1, 1024>>>(tf);
    lp_kernel<<<PPW / 256, 256>>>(W);          // 1600 blocks
    dim3 grid(4, COUT / TOC, B_);              // (2x2 spatial, 16 ch-groups, 16 b)
    conv_kernel<<<grid, 256>>>(x, out);
}

// round 4
// speedup vs baseline: 7.3695x; 3.1983x over previous
#include <cuda_runtime.h>
#include <cstdint>

#define B_    16
#define T_    8
#define KBANK 64
#define COUT  128
#define CIN   128
#define HH    64
#define WW    64
#define HP    68
#define WP    68
#define PPW   (COUT * CIN * 25)        // 409600

// ---------------- device scratch (allocation-free) ----------------
__device__ float g_coeff[B_ * KBANK];
__device__ float g_lp[(size_t)B_ * PPW];                   // fp32 [b][o][c][tap]
__device__ unsigned g_A[(size_t)B_ * 25 * CIN * COUT];     // tf32 [b][tap][c][o]
__device__ unsigned g_xp[(size_t)B_ * CIN * HP * WP];      // tf32 [b][c][hp][wp], zero-pad

// ---------------- PTX helpers ----------------
__device__ __forceinline__ uint32_t smem_u32(const void* p) {
    uint32_t a;
    asm("{ .reg .u64 t; cvta.to.shared.u64 t, %1; cvt.u32.u64 %0, t; }" : "=r"(a) : "l"(p));
    return a;
}
__device__ __forceinline__ uint32_t f2tf32(float v) {
    uint32_t r; asm("cvt.rna.tf32.f32 %0, %1;" : "=r"(r) : "f"(v)); return r;
}
#define CP16(smem, gmem) \
    asm volatile("cp.async.cg.shared.global [%0], [%1], 16;" :: "r"(smem), "l"(gmem))
#define CP_COMMIT() asm volatile("cp.async.commit_group;" ::: "memory")
#define CP_WAIT0()  asm volatile("cp.async.wait_group 0;" ::: "memory")

#define MMA1688(c, a, b0v, b1v) \
    asm volatile("mma.sync.aligned.m16n8k8.row.col.f32.tf32.tf32.f32 " \
        "{%0,%1,%2,%3}, {%4,%5,%6,%7}, {%8,%9}, {%0,%1,%2,%3};" \
        : "+f"((c)[0]), "+f"((c)[1]), "+f"((c)[2]), "+f"((c)[3]) \
        : "r"((a)[0]), "r"((a)[1]), "r"((a)[2]), "r"((a)[3]), "r"(b0v), "r"(b1v))

// ---------------------------------------------------------------------------
// K0: coeff[b,k] = mean_t tf[b,t,k]
// ---------------------------------------------------------------------------
__global__ void coeff_kernel(const float* __restrict__ tf) {
    int tid = threadIdx.x;
    int b = tid >> 6, k = tid & 63;
    float s = 0.f;
#pragma unroll
    for (int t = 0; t < T_; t++) s += tf[((b * T_ + t) * KBANK) + k];
    g_coeff[tid] = s * (1.0f / (float)T_);
}

// ---------------------------------------------------------------------------
// K1: g_lp[b][p] = sum_k coeff[b][k] * W[k][p]
// ---------------------------------------------------------------------------
__global__ __launch_bounds__(256) void lp_kernel(const float* __restrict__ W) {
    __shared__ float sc[B_ * KBANK];
    int tid = threadIdx.x;
    for (int i = tid; i < B_ * KBANK; i += 256) sc[i] = g_coeff[i];
    __syncthreads();
    size_t p = (size_t)blockIdx.x * 256 + tid;
    float acc[B_];
#pragma unroll
    for (int b = 0; b < B_; b++) acc[b] = 0.f;
    for (int k = 0; k < KBANK; k++) {
        float wv = W[(size_t)k * PPW + p];
#pragma unroll
        for (int b = 0; b < B_; b++) acc[b] = fmaf(sc[b * KBANK + k], wv, acc[b]);
    }
#pragma unroll
    for (int b = 0; b < B_; b++) g_lp[(size_t)b * PPW + p] = acc[b];
}

// ---------------------------------------------------------------------------
// K2: g_A[b][tap][c][o] = tf32(lp[b][o][c][tap]);  grid (c=128, b=16), 128 thr (o)
// ---------------------------------------------------------------------------
__global__ __launch_bounds__(128) void atrans_kernel() {
    int c = blockIdx.x, b = blockIdx.y, o = threadIdx.x;
    const float* src = g_lp + (((size_t)b * COUT + o) * CIN + c) * 25;
    float v[25];
#pragma unroll
    for (int ij = 0; ij < 25; ij++) v[ij] = src[ij];
#pragma unroll
    for (int ij = 0; ij < 25; ij++)
        g_A[(((size_t)b * 25 + ij) * CIN + c) * COUT + o] = f2tf32(v[ij]);
}

// ---------------------------------------------------------------------------
// K3: g_xp[b][c][hp][wp] = tf32(x[b][c][hp-2][wp-2]), zero pad
// ---------------------------------------------------------------------------
__global__ __launch_bounds__(256) void xpad_kernel(const float* __restrict__ x) {
    size_t idx = (size_t)blockIdx.x * 256 + threadIdx.x;
    if (idx >= (size_t)B_ * CIN * HP * WP) return;
    int wp = idx % WP;
    int hp = (idx / WP) % HP;
    size_t bc = idx / (HP * WP);         // b*128 + c
    float v = 0.f;
    int h = hp - 2, w = wp - 2;
    if ((unsigned)h < HH && (unsigned)w < WW)
        v = x[bc * HH * WW + (size_t)h * WW + w];
    g_xp[idx] = f2tf32(v);
}

// ---------------------------------------------------------------------------
// K4: conv as 25 tap-GEMMs via mma.sync m16n8k8 tf32.
// CTA = (b, 4 output rows): D[128 cout, 256 px]. 512 thr, 16 warps (4M x 4N),
// warp tile 32x64. cin chunks of 32: B halo [32][8*68] pitch 552 (1x per chunk),
// A [32][128] pitch 136 double-buffered per tap via cp.async.
// ---------------------------------------------------------------------------
#define SA_PITCH 136
#define SB_PITCH 552
#define SA0 0
#define SA1 (32 * SA_PITCH)            // 4352
#define SBO (2 * 32 * SA_PITCH)        // 8704
#define SM_WORDS (SBO + 32 * SB_PITCH) // 26368 words = 105472 B

__device__ __forceinline__ void stage_a(uint32_t sb, const char* Abase,
                                        int cc, int tap, int buf) {
    int t0 = threadIdx.x;
    uint32_t dbase = sb + (buf ? SA1 : SA0) * 4;
#pragma unroll
    for (int i = 0; i < 2; i++) {
        int idx = t0 + (i << 9);               // < 1024
        int k = idx >> 5, f = idx & 31;        // k: cin in chunk, f: float4 of couts
        const char* src = Abase + ((size_t)((tap * CIN) + cc * 32 + k) * COUT + f * 4) * 4;
        CP16(dbase + (uint32_t)(k * SA_PITCH + f * 4) * 4, src);
    }
}

__global__ __launch_bounds__(512, 1) void conv_kernel(float* __restrict__ out) {
    extern __shared__ uint32_t sm[];
    const uint32_t sb = smem_u32(sm);
    const int tid = threadIdx.x;
    const int lane = tid & 31;
    const int wid = tid >> 5;
    const int g = lane >> 2, t = lane & 3;
    const int warp_m = wid & 3;        // 4 groups of 32 couts
    const int warp_n = wid >> 2;       // 4 output rows (64 px each)
    const int b = blockIdx.y, h0 = blockIdx.x * 4;

    const char* Abase = (const char*)g_A + (size_t)b * 25 * CIN * COUT * 4;
    const char* Xbase = (const char*)g_xp + (size_t)b * CIN * HP * WP * 4;

    float acc[2][8][4];
#pragma unroll
    for (int mt = 0; mt < 2; mt++)
#pragma unroll
        for (int nt = 0; nt < 8; nt++)
#pragma unroll
            for (int q = 0; q < 4; q++) acc[mt][nt][q] = 0.f;

    for (int cc = 0; cc < 4; cc++) {
        // ---- stage B halo: rows h0..h0+7 (padded), all 68 cols, 32 cin ----
        for (int idx = tid; idx < 4352; idx += 512) {
            int k = idx / 136, rem = idx - k * 136;
            int r = rem / 17, f = rem - r * 17;   // 17 float4 per 68-col row
            const char* src = Xbase +
                ((size_t)((cc * 32 + k) * HP + h0 + r) * WP + f * 4) * 4;
            CP16(sb + (uint32_t)(SBO + k * SB_PITCH + r * WP + f * 4) * 4, src);
        }
        stage_a(sb, Abase, cc, 0, 0);
        CP_COMMIT(); CP_WAIT0(); __syncthreads();

        for (int tap = 0; tap < 25; tap++) {
            const int buf = tap & 1;
            if (tap + 1 < 25) { stage_a(sb, Abase, cc, tap + 1, buf ^ 1); CP_COMMIT(); }
            const int di = tap / 5, dj = tap % 5;
            const uint32_t* sA = sm + (buf ? SA1 : SA0);
            const uint32_t* sB = sm + SBO;
            const int bbase = (warp_n + di) * WP + dj + g;   // pixel word offset

#pragma unroll
            for (int kk = 0; kk < 4; kk++) {
                uint32_t a[2][4];
#pragma unroll
                for (int mt = 0; mt < 2; mt++) {
                    const uint32_t* ap = sA + (kk * 8 + t) * SA_PITCH
                                            + warp_m * 32 + mt * 16 + g;
                    a[mt][0] = ap[0];
                    a[mt][1] = ap[8];
                    a[mt][2] = ap[4 * SA_PITCH];
                    a[mt][3] = ap[4 * SA_PITCH + 8];
                }
                const uint32_t* bp0 = sB + (kk * 8 + t) * SB_PITCH + bbase;
                const uint32_t* bp1 = bp0 + 4 * SB_PITCH;
#pragma unroll
                for (int nt = 0; nt < 8; nt++) {
                    uint32_t b0 = bp0[nt * 8], b1 = bp1[nt * 8];
                    MMA1688(acc[0][nt], a[0], b0, b1);
                    MMA1688(acc[1][nt], a[1], b0, b1);
                }
            }
            CP_WAIT0(); __syncthreads();
        }
    }

    // ---- epilogue: c0=D[g][2t], c1=D[g][2t+1], c2=D[g+8][2t], c3=D[g+8][2t+1]
    const int h = h0 + warp_n;
#pragma unroll
    for (int mt = 0; mt < 2; mt++) {
#pragma unroll
        for (int rr = 0; rr < 2; rr++) {
            int cout = warp_m * 32 + mt * 16 + g + rr * 8;
            float* op = out + (((size_t)b * COUT + cout) * HH + h) * WW;
#pragma unroll
            for (int nt = 0; nt < 8; nt++) {
                float2 v = make_float2(acc[mt][nt][rr * 2], acc[mt][nt][rr * 2 + 1]);
                *(float2*)(op + nt * 8 + 2 * t) = v;
            }
        }
    }
}

// ---------------------------------------------------------------------------
extern "C" void kernel_launch(void* const* d_in, const int* in_sizes, int n_in,
                              void* d_out, int out_size) {
    (void)in_sizes; (void)n_in; (void)out_size;
    const float* x  = (const float*)d_in[0];   // (16,128,64,64)
    const float* tf = (const float*)d_in[1];   // (16,8,64)
    const float* W  = (const float*)d_in[2];   // (64,128,128,5,5)
    float* out = (float*)d_out;                // (16,128,64,64)

    cudaFuncSetAttribute(conv_kernel, cudaFuncAttributeMaxDynamicSharedMemorySize,
                         SM_WORDS * 4);

    coeff_kernel<<<1, 1024>>>(tf);
    lp_kernel<<<PPW / 256, 256>>>(W);
    atrans_kernel<<<dim3(CIN, B_), 128>>>();
    {
        size_t n = (size_t)B_ * CIN * HP * WP;
        xpad_kernel<<<(unsigned)((n + 255) / 256), 256>>>(x);
    }
    conv_kernel<<<dim3(HH / 4, B_), 512, SM_WORDS * 4>>>(out);
}

// round 5
// speedup vs baseline: 11.4012x; 1.5471x over previous
#include <cuda_runtime.h>
#include <cuda_fp16.h>
#include <cstdint>

#define B_    16
#define T_    8
#define KBANK 64
#define COUT  128
#define CIN   128
#define HH    64
#define WW    64
#define HP    68
#define WP    68
#define PPW   (COUT * CIN * 25)        // 409600

// ---------------- device scratch (allocation-free) ----------------
__device__ float g_lp[(size_t)B_ * PPW];                       // fp32 [b][o][c][tap]
__device__ unsigned g_Ah[(size_t)B_ * 25 * COUT * (CIN / 2)];  // half2 [b][tap][o][cpair]
__device__ unsigned g_xph[(size_t)B_ * (CIN / 2) * HP * WP];   // half2 [b][cpair][hp][wp]

// ---------------- PTX helpers ----------------
__device__ __forceinline__ uint32_t smem_u32(const void* p) {
    uint32_t a;
    asm("{ .reg .u64 t; cvta.to.shared.u64 t, %1; cvt.u32.u64 %0, t; }" : "=r"(a) : "l"(p));
    return a;
}
#define CP16(smem, gmem) \
    asm volatile("cp.async.cg.shared.global [%0], [%1], 16;" :: "r"(smem), "l"(gmem))
#define CP_COMMIT() asm volatile("cp.async.commit_group;" ::: "memory")
#define CP_WAIT0()  asm volatile("cp.async.wait_group 0;" ::: "memory")

#define MMA16816(c, a, b0v, b1v) \
    asm volatile("mma.sync.aligned.m16n8k16.row.col.f32.f16.f16.f32 " \
        "{%0,%1,%2,%3}, {%4,%5,%6,%7}, {%8,%9}, {%0,%1,%2,%3};" \
        : "+f"((c)[0]), "+f"((c)[1]), "+f"((c)[2]), "+f"((c)[3]) \
        : "r"((a)[0]), "r"((a)[1]), "r"((a)[2]), "r"((a)[3]), "r"(b0v), "r"(b1v))

// ---------------------------------------------------------------------------
// K1: coeff (fused, recomputed per block) + g_lp[b][p] = sum_k coeff[b][k]*W[k][p]
// ---------------------------------------------------------------------------
__global__ __launch_bounds__(256) void lp_kernel(const float* __restrict__ W,
                                                 const float* __restrict__ tf) {
    __shared__ float sc[B_ * KBANK];
    int tid = threadIdx.x;
    for (int i = tid; i < B_ * KBANK; i += 256) {
        int b = i >> 6, k = i & 63;
        float s = 0.f;
#pragma unroll
        for (int t = 0; t < T_; t++) s += tf[(b * T_ + t) * KBANK + k];
        sc[i] = s * (1.0f / (float)T_);
    }
    __syncthreads();
    size_t p = (size_t)blockIdx.x * 256 + tid;
    float acc[B_];
#pragma unroll
    for (int b = 0; b < B_; b++) acc[b] = 0.f;
    for (int k = 0; k < KBANK; k++) {
        float wv = W[(size_t)k * PPW + p];
#pragma unroll
        for (int b = 0; b < B_; b++) acc[b] = fmaf(sc[b * KBANK + k], wv, acc[b]);
    }
#pragma unroll
    for (int b = 0; b < B_; b++) g_lp[(size_t)b * PPW + p] = acc[b];
}

// ---------------------------------------------------------------------------
// K2: g_Ah[b][tap][o][cp] = half2(lp[b][o][2cp][tap], lp[b][o][2cp+1][tap])
// grid (o=128, b=16), 64 threads (cp)
// ---------------------------------------------------------------------------
__global__ __launch_bounds__(64) void atrans_kernel() {
    int o = blockIdx.x, b = blockIdx.y, cp = threadIdx.x;
    const float* src = g_lp + (((size_t)b * COUT + o) * CIN + 2 * cp) * 25;
    unsigned* dst = g_Ah + ((size_t)b * 25 * COUT + o) * 64 + cp;
#pragma unroll 5
    for (int ij = 0; ij < 25; ij++) {
        __half2 h = __floats2half2_rn(src[ij], src[25 + ij]);
        dst[(size_t)ij * COUT * 64] = *(unsigned*)&h;
    }
}

// ---------------------------------------------------------------------------
// K3: g_xph[b][cp][hp][wp] = half2(x[b][2cp][h][w], x[b][2cp+1][h][w]) / zero pad
// ---------------------------------------------------------------------------
__global__ __launch_bounds__(256) void xpad_kernel(const float* __restrict__ x) {
    size_t idx = (size_t)blockIdx.x * 256 + threadIdx.x;
    if (idx >= (size_t)B_ * 64 * HP * WP) return;
    int wp = idx % WP;
    int hp = (idx / WP) % HP;
    size_t bcp = idx / (HP * WP);        // b*64 + cp
    size_t b = bcp >> 6, cp = bcp & 63;
    float v0 = 0.f, v1 = 0.f;
    int h = hp - 2, w = wp - 2;
    if ((unsigned)h < HH && (unsigned)w < WW) {
        const float* xp = x + ((b * CIN + 2 * cp) * HH + h) * WW + w;
        v0 = xp[0];
        v1 = xp[HH * WW];
    }
    __half2 hh = __floats2half2_rn(v0, v1);
    g_xph[idx] = *(unsigned*)&hh;
}

// ---------------------------------------------------------------------------
// K4: conv as 25 tap-GEMMs via mma.sync m16n8k16 fp16 (fp32 accum).
// CTA = (b, 4 output rows): D[128 cout, 256 px]. 512 thr, 16 warps (4M x 4N).
// cin chunks of 32 (16 cpairs): B halo [16 cp][8 rows x 68] pitch 552,
// A [128 o][16 cp] pitch 20, double-buffered per tap via cp.async.
// ---------------------------------------------------------------------------
#define AP  20
#define BP  552
#define SA0 0
#define SA1 (128 * AP)                 // 2560
#define SBOFF (2 * 128 * AP)           // 5120
#define SMW (SBOFF + 16 * BP)          // 13952 words = 55808 B

__device__ __forceinline__ void stage_a(uint32_t sb, const unsigned* Abase,
                                        int cc, int tap, int buf) {
    int o = threadIdx.x >> 2, f = threadIdx.x & 3;
    const unsigned* src = Abase + ((size_t)tap * COUT + o) * 64 + cc * 16 + f * 4;
    uint32_t dst = sb + (uint32_t)((buf ? SA1 : SA0) + o * AP + f * 4) * 4;
    CP16(dst, src);
}

__global__ __launch_bounds__(512, 1) void conv_kernel(float* __restrict__ out) {
    extern __shared__ uint32_t sm[];
    const uint32_t sb = smem_u32(sm);
    const int tid = threadIdx.x;
    const int lane = tid & 31;
    const int wid = tid >> 5;
    const int g = lane >> 2, t = lane & 3;
    const int warp_m = wid & 3;        // 4 groups of 32 couts
    const int warp_n = wid >> 2;       // 4 output rows
    const int b = blockIdx.y, h0 = blockIdx.x * 4;

    const unsigned* Abase = g_Ah + (size_t)b * 25 * COUT * 64;
    const unsigned* Xbase = g_xph + (size_t)b * 64 * HP * WP;

    float acc[2][8][4];
#pragma unroll
    for (int mt = 0; mt < 2; mt++)
#pragma unroll
        for (int nt = 0; nt < 8; nt++)
#pragma unroll
            for (int q = 0; q < 4; q++) acc[mt][nt][q] = 0.f;

    for (int cc = 0; cc < 4; cc++) {
        // ---- stage B halo: 16 cpairs x 8 padded rows x 68 cols ----
        for (int idx = tid; idx < 2176; idx += 512) {
            int cp = idx / 136, rem = idx - cp * 136;
            int r = rem / 17, f = rem - r * 17;
            const unsigned* src = Xbase + (size_t)(cc * 16 + cp) * HP * WP
                                        + (h0 + r) * WP + f * 4;
            CP16(sb + (uint32_t)(SBOFF + cp * BP + r * WP + f * 4) * 4, src);
        }
        stage_a(sb, Abase, cc, 0, 0);
        CP_COMMIT(); CP_WAIT0(); __syncthreads();

        for (int tap = 0; tap < 25; tap++) {
            const int buf = tap & 1;
            if (tap + 1 < 25) { stage_a(sb, Abase, cc, tap + 1, buf ^ 1); CP_COMMIT(); }
            const int di = tap / 5, dj = tap % 5;
            const uint32_t* sA = sm + (buf ? SA1 : SA0);
            const uint32_t* sB = sm + SBOFF;
            const int bbase = (warp_n + di) * WP + dj + g;

#pragma unroll
            for (int kk = 0; kk < 2; kk++) {
                uint32_t a[2][4];
#pragma unroll
                for (int mt = 0; mt < 2; mt++) {
                    const uint32_t* ap = sA + (warp_m * 32 + mt * 16 + g) * AP
                                            + kk * 8 + t;
                    a[mt][0] = ap[0];            // row g,   cpair t
                    a[mt][1] = ap[8 * AP];       // row g+8, cpair t
                    a[mt][2] = ap[4];            // row g,   cpair t+4
                    a[mt][3] = ap[8 * AP + 4];   // row g+8, cpair t+4
                }
                const uint32_t* bp0 = sB + (kk * 8 + t) * BP + bbase;
                const uint32_t* bp1 = bp0 + 4 * BP;
#pragma unroll
                for (int nt = 0; nt < 8; nt++) {
                    uint32_t b0 = bp0[nt * 8], b1 = bp1[nt * 8];
                    MMA16816(acc[0][nt], a[0], b0, b1);
                    MMA16816(acc[1][nt], a[1], b0, b1);
                }
            }
            CP_WAIT0(); __syncthreads();
        }
    }

    // ---- epilogue ----
    const int h = h0 + warp_n;
#pragma unroll
    for (int mt = 0; mt < 2; mt++) {
#pragma unroll
        for (int rr = 0; rr < 2; rr++) {
            int cout = warp_m * 32 + mt * 16 + g + rr * 8;
            float* op = out + (((size_t)b * COUT + cout) * HH + h) * WW;
#pragma unroll
            for (int nt = 0; nt < 8; nt++) {
                float2 v = make_float2(acc[mt][nt][rr * 2], acc[mt][nt][rr * 2 + 1]);
                *(float2*)(op + nt * 8 + 2 * t) = v;
            }
        }
    }
}

// ---------------------------------------------------------------------------
extern "C" void kernel_launch(void* const* d_in, const int* in_sizes, int n_in,
                              void* d_out, int out_size) {
    (void)in_sizes; (void)n_in; (void)out_size;
    const float* x  = (const float*)d_in[0];   // (16,128,64,64)
    const float* tf = (const float*)d_in[1];   // (16,8,64)
    const float* W  = (const float*)d_in[2];   // (64,128,128,5,5)
    float* out = (float*)d_out;                // (16,128,64,64)

    cudaFuncSetAttribute(conv_kernel, cudaFuncAttributeMaxDynamicSharedMemorySize,
                         SMW * 4);

    lp_kernel<<<PPW / 256, 256>>>(W, tf);
    atrans_kernel<<<dim3(COUT, B_), 64>>>();
    {
        size_t n = (size_t)B_ * 64 * HP * WP;
        xpad_kernel<<<(unsigned)((n + 255) / 256), 256>>>(x);
    }
    conv_kernel<<<dim3(HH / 4, B_), 512, SMW * 4>>>(out);
}